// round 13
// baseline (speedup 1.0000x reference)
#include <cuda_runtime.h>
#include <cstdint>

// Problem constants
#define BATCH 8
#define SEQ   1025
#define EMB   768
#define NH    12
#define HD    64
#define MROWS (BATCH*SEQ)      // 8200
#define NQKV  (3*EMB)          // 2304
#define RPP   1026             // RPB row pitch (even -> float2-aligned rows)
#define LOG2E 1.4426950408889634f

// ---------------------------------------------------------------------------
// Scratch (device globals; allocation-free per harness rules)
// ---------------------------------------------------------------------------
__device__ __align__(16) float g_q  [BATCH*NH*SEQ*HD];   // q pre-scaled (x log2e), tf32
__device__ __align__(16) float g_k  [BATCH*NH*SEQ*HD];   // tf32
__device__ __align__(16) float g_v  [BATCH*NH*SEQ*HD];   // tf32
__device__ __align__(16) float g_ao [MROWS*EMB];         // attn out, tf32, k-permuted
__device__ __align__(16) float g_rpb[NH*SEQ*RPP + 256];  // [H][N][RPP] x log2e
__device__ __align__(16) float g_xt [MROWS*EMB];         // X  tf32, k-permuted
__device__ __align__(16) float g_wt [NQKV*EMB];          // qkv_w tf32, k-permuted
__device__ __align__(16) float g_pwt[EMB*EMB];           // proj_w tf32, k-permuted

// ---------------------------------------------------------------------------
// helpers
// ---------------------------------------------------------------------------
__device__ __forceinline__ float cvt_tf32(float x) {
    uint32_t u;
    asm("cvt.rna.tf32.f32 %0, %1;" : "=r"(u) : "f"(x));
    return __uint_as_float(u);
}
__device__ __forceinline__ uint32_t cvt_tf32_u(float x) {
    uint32_t u;
    asm("cvt.rna.tf32.f32 %0, %1;" : "=r"(u) : "f"(x));
    return u;
}
__device__ __forceinline__ float fexp2(float x) {
    float y;
    asm("ex2.approx.f32 %0, %1;" : "=f"(y) : "f"(x));
    return y;
}

__device__ __forceinline__ void mma_tf32(float* d,
                                         const uint32_t* a,
                                         const uint32_t* b)
{
    asm volatile(
        "mma.sync.aligned.m16n8k8.row.col.f32.tf32.tf32.f32 "
        "{%0,%1,%2,%3}, {%4,%5,%6,%7}, {%8,%9}, {%0,%1,%2,%3};\n"
        : "+f"(d[0]), "+f"(d[1]), "+f"(d[2]), "+f"(d[3])
        : "r"(a[0]), "r"(a[1]), "r"(a[2]), "r"(a[3]),
          "r"(b[0]), "r"(b[1]));
}

__device__ __forceinline__ void cp_async16(void* smem_dst, const void* gptr) {
    uint32_t sa = (uint32_t)__cvta_generic_to_shared(smem_dst);
    asm volatile("cp.async.cg.shared.global [%0], [%1], 16;\n"
                 :: "r"(sa), "l"(gptr));
}
#define CP_COMMIT()  asm volatile("cp.async.commit_group;\n")
#define CP_WAIT0()   asm volatile("cp.async.wait_group 0;\n")

// ---------------------------------------------------------------------------
// Kernel 0: tf32 round + k-group permute.
// Within each 8-float k-group, dst order = [k0,k4,k1,k5,k2,k6,k3,k7]:
// thread (g,tg)'s mma fragment pair (k=tg, k=tg+4) becomes one float2.
// One thread per 8-float group.
// ---------------------------------------------------------------------------
__global__ void tf32_round_perm_kernel(const float* __restrict__ src,
                                       float* __restrict__ dst, int ngrp)
{
    int i = blockIdx.x * blockDim.x + threadIdx.x;
    if (i >= ngrp) return;
    float4 a = *(const float4*)&src[8 * i];      // k0..k3
    float4 b = *(const float4*)&src[8 * i + 4];  // k4..k7
    float4 lo = make_float4(cvt_tf32(a.x), cvt_tf32(b.x),
                            cvt_tf32(a.y), cvt_tf32(b.y));
    float4 hi = make_float4(cvt_tf32(a.z), cvt_tf32(b.z),
                            cvt_tf32(a.w), cvt_tf32(b.w));
    *(float4*)&dst[8 * i]     = lo;
    *(float4*)&dst[8 * i + 4] = hi;
}

// ---------------------------------------------------------------------------
// Kernel 1: gather rel-pos bias -> dense [H][N][RPP], scaled by log2(e)
// ---------------------------------------------------------------------------
__global__ void rpb_gather_kernel(const float* __restrict__ table,
                                  const int* __restrict__ relidx)
{
    int t = blockIdx.x * blockDim.x + threadIdx.x;
    const int total = NH * SEQ * SEQ;
    if (t >= total) return;
    int h  = t / (SEQ * SEQ);
    int qk = t - h * (SEQ * SEQ);
    int q  = qk / SEQ;
    int k  = qk - q * SEQ;
    g_rpb[((size_t)h * SEQ + q) * RPP + k] = table[relidx[qk] * NH + h] * LOG2E;
}

// ---------------------------------------------------------------------------
// tf32 TC GEMM: 128x128 tile, BK=32, 2-stage cp.async, single sync/iter.
// Operands are tf32-pre-rounded AND k-permuted -> float2 fragment loads.
// ---------------------------------------------------------------------------
#define GP 36
#define GSTG (128 * GP)
#define GEMM_SMEM_BYTES (4 * GSTG * 4)   // 73728 B
#define KBLK (EMB / 32)                  // 24

__device__ __forceinline__ void gemm_stage_load(
    float* As, float* Bs, const float* __restrict__ Agm,
    const float* __restrict__ Bgm, int m0, int n0, int k0, int tid)
{
    #pragma unroll
    for (int r = 0; r < 4; r++) {
        int f   = tid + r * 256;
        int row = f >> 3;
        int c4  = (f & 7) << 2;
        int gr  = m0 + row; if (gr > MROWS - 1) gr = MROWS - 1;
        cp_async16(&As[row * GP + c4], &Agm[(size_t)gr * EMB + k0 + c4]);
        cp_async16(&Bs[row * GP + c4], &Bgm[(size_t)(n0 + row) * EMB + k0 + c4]);
    }
}

__device__ __forceinline__ void gemm_stage_compute(
    const float* As, const float* Bs, float acc[4][4][4],
    int wm, int wn, int g, int tg)
{
    #pragma unroll
    for (int ks = 0; ks < 4; ks++) {
        const int kb = ks * 8 + 2 * tg;
        uint32_t afr[4][4];
        #pragma unroll
        for (int mi = 0; mi < 4; mi++) {
            float2 lo = *(const float2*)&As[(wm + mi * 16 + g) * GP + kb];
            float2 hi = *(const float2*)&As[(wm + mi * 16 + g + 8) * GP + kb];
            afr[mi][0] = __float_as_uint(lo.x);  // (row g,   k=tg)
            afr[mi][1] = __float_as_uint(hi.x);  // (row g+8, k=tg)
            afr[mi][2] = __float_as_uint(lo.y);  // (row g,   k=tg+4)
            afr[mi][3] = __float_as_uint(hi.y);  // (row g+8, k=tg+4)
        }
        uint32_t bfr[4][2];
        #pragma unroll
        for (int ni = 0; ni < 4; ni++) {
            float2 bv = *(const float2*)&Bs[(wn + ni * 8 + g) * GP + kb];
            bfr[ni][0] = __float_as_uint(bv.x);
            bfr[ni][1] = __float_as_uint(bv.y);
        }
        #pragma unroll
        for (int mi = 0; mi < 4; mi++)
            #pragma unroll
            for (int ni = 0; ni < 4; ni++)
                mma_tf32(acc[mi][ni], afr[mi], bfr[ni]);
    }
}

// Kernel 2: QKV  C[M,2304] = Xt @ Wt^T (+bias/scale/scatter; q gets log2e)
__global__ __launch_bounds__(256, 2)
void qkv_gemm_tc(const float* __restrict__ q_bias,
                 const float* __restrict__ v_bias)
{
    extern __shared__ float smp[];
    const int m0  = blockIdx.x * 128;
    const int n0  = blockIdx.y * 128;
    const int tid = threadIdx.x;
    const int wid  = tid >> 5;
    const int lane = tid & 31;
    const int g  = lane >> 2;
    const int tg = lane & 3;
    const int wm = (wid >> 2) * 64;
    const int wn = (wid & 3) * 32;

    float acc[4][4][4];
    #pragma unroll
    for (int mi = 0; mi < 4; mi++)
        #pragma unroll
        for (int ni = 0; ni < 4; ni++)
            #pragma unroll
            for (int r = 0; r < 4; r++) acc[mi][ni][r] = 0.f;

    gemm_stage_load(smp, smp + GSTG, g_xt, g_wt, m0, n0, 0, tid);
    CP_COMMIT();

    for (int it = 0; it < KBLK; it++) {
        float* As = smp + (it & 1) * 2 * GSTG;
        CP_WAIT0();
        __syncthreads();
        if (it + 1 < KBLK) {
            float* An = smp + ((it + 1) & 1) * 2 * GSTG;
            gemm_stage_load(An, An + GSTG, g_xt, g_wt, m0, n0,
                            (it + 1) * 32, tid);
            CP_COMMIT();
        }
        gemm_stage_compute(As, As + GSTG, acc, wm, wn, g, tg);
    }

    const float scale = 0.125f * LOG2E;
    #pragma unroll
    for (int mi = 0; mi < 4; mi++) {
        #pragma unroll
        for (int h2 = 0; h2 < 2; h2++) {
            int gr = m0 + wm + mi * 16 + g + h2 * 8;
            if (gr >= MROWS) continue;
            int b = gr / SEQ;
            int n = gr - b * SEQ;
            #pragma unroll
            for (int ni = 0; ni < 4; ni++) {
                int gc    = n0 + wn + ni * 8 + 2 * tg;
                int which = gc / EMB;
                int rem   = gc - which * EMB;
                int h     = rem >> 6;
                int d     = rem & 63;
                float v0 = acc[mi][ni][h2 * 2 + 0];
                float v1 = acc[mi][ni][h2 * 2 + 1];
                size_t off = ((size_t)(b * NH + h) * SEQ + n) * HD + d;
                if (which == 0) {
                    *(float2*)&g_q[off] =
                        make_float2(cvt_tf32((v0 + q_bias[rem]) * scale),
                                    cvt_tf32((v1 + q_bias[rem + 1]) * scale));
                } else if (which == 1) {
                    *(float2*)&g_k[off] =
                        make_float2(cvt_tf32(v0), cvt_tf32(v1));
                } else {
                    *(float2*)&g_v[off] =
                        make_float2(cvt_tf32(v0 + v_bias[rem]),
                                    cvt_tf32(v1 + v_bias[rem + 1]));
                }
            }
        }
    }
}

// Kernel 4: proj  out[M,768] = AO @ Pwt^T + bias  (AO, Pwt k-permuted)
__global__ __launch_bounds__(256, 2)
void proj_gemm_tc(const float* __restrict__ bias,
                  float* __restrict__ out)
{
    extern __shared__ float smp[];
    const int m0  = blockIdx.x * 128;
    const int n0  = blockIdx.y * 128;
    const int tid = threadIdx.x;
    const int wid  = tid >> 5;
    const int lane = tid & 31;
    const int g  = lane >> 2;
    const int tg = lane & 3;
    const int wm = (wid >> 2) * 64;
    const int wn = (wid & 3) * 32;

    float acc[4][4][4];
    #pragma unroll
    for (int mi = 0; mi < 4; mi++)
        #pragma unroll
        for (int ni = 0; ni < 4; ni++)
            #pragma unroll
            for (int r = 0; r < 4; r++) acc[mi][ni][r] = 0.f;

    gemm_stage_load(smp, smp + GSTG, g_ao, g_pwt, m0, n0, 0, tid);
    CP_COMMIT();

    for (int it = 0; it < KBLK; it++) {
        float* As = smp + (it & 1) * 2 * GSTG;
        CP_WAIT0();
        __syncthreads();
        if (it + 1 < KBLK) {
            float* An = smp + ((it + 1) & 1) * 2 * GSTG;
            gemm_stage_load(An, An + GSTG, g_ao, g_pwt, m0, n0,
                            (it + 1) * 32, tid);
            CP_COMMIT();
        }
        gemm_stage_compute(As, As + GSTG, acc, wm, wn, g, tg);
    }

    #pragma unroll
    for (int mi = 0; mi < 4; mi++) {
        #pragma unroll
        for (int h2 = 0; h2 < 2; h2++) {
            int gr = m0 + wm + mi * 16 + g + h2 * 8;
            if (gr >= MROWS) continue;
            #pragma unroll
            for (int ni = 0; ni < 4; ni++) {
                int gc = n0 + wn + ni * 8 + 2 * tg;
                *(float2*)&out[(size_t)gr * EMB + gc] =
                    make_float2(acc[mi][ni][h2 * 2 + 0] + bias[gc],
                                acc[mi][ni][h2 * 2 + 1] + bias[gc + 1]);
            }
        }
    }
}

// ---------------------------------------------------------------------------
// Kernel 3: tf32 tensor-core flash attention (scores in log2 domain)
// ---------------------------------------------------------------------------
#define AQ 128
#define AK 64
#define AP 68
#define ATT_SMEM_BYTES ((AQ*AP + 2*AK*AP) * 4)   // 69632

__global__ __launch_bounds__(256, 2)
void attn_tc_kernel()
{
    extern __shared__ float sm[];
    float* sQ = sm;                 // [128][68]
    float* sK = sQ + AQ * AP;       // [64][68]
    float* sV = sK + AK * AP;       // [64][68]

    const int qt = blockIdx.x;
    const int h  = blockIdx.y;
    const int b  = blockIdx.z;
    const int q0 = qt * AQ;
    const int tid  = threadIdx.x;
    const int w    = tid >> 5;
    const int lane = tid & 31;
    const int g  = lane >> 2;
    const int tg = lane & 3;

    const size_t bh = (size_t)(b * NH + h) * SEQ * HD;
    const float* qbase = g_q + bh;
    const float* kbase = g_k + bh;
    const float* vbase = g_v + bh;

    for (int f = tid; f < AQ * 16; f += 256) {
        int row = f >> 4;
        int c4  = (f & 15) << 2;
        int qr  = q0 + row;
        float4 v4;
        if (qr < SEQ) v4 = *(const float4*)&qbase[(size_t)qr * HD + c4];
        else          v4 = make_float4(0.f, 0.f, 0.f, 0.f);
        *(float4*)&sQ[row * AP + c4] = v4;
    }
    __syncthreads();

    uint32_t qf[8][4];
    #pragma unroll
    for (int c = 0; c < 8; c++) {
        int base = (16 * w + g) * AP + 8 * c + tg;
        qf[c][0] = __float_as_uint(sQ[base]);
        qf[c][1] = __float_as_uint(sQ[base + 8 * AP]);
        qf[c][2] = __float_as_uint(sQ[base + 4]);
        qf[c][3] = __float_as_uint(sQ[base + 8 * AP + 4]);
    }

    const int qi0 = q0 + 16 * w + g;
    const int qi1 = qi0 + 8;
    const int qc0 = (qi0 < SEQ) ? qi0 : (SEQ - 1);
    const int qc1 = (qi1 < SEQ) ? qi1 : (SEQ - 1);
    const float* rp0 = g_rpb + ((size_t)h * SEQ + qc0) * RPP;
    const float* rp1 = g_rpb + ((size_t)h * SEQ + qc1) * RPP;

    float o[8][4];
    #pragma unroll
    for (int nj = 0; nj < 8; nj++)
        #pragma unroll
        for (int r = 0; r < 4; r++) o[nj][r] = 0.f;
    float m0r = -3.0e38f, m1r = -3.0e38f;
    float l0r = 0.f,      l1r = 0.f;

    for (int k0 = 0; k0 < SEQ; k0 += AK) {
        __syncthreads();
        for (int f = tid; f < AK * 16; f += 256) {
            int row = f >> 4;
            int c4  = (f & 15) << 2;
            int kr  = k0 + row;
            float4 kv, vv;
            if (kr < SEQ) {
                kv = *(const float4*)&kbase[(size_t)kr * HD + c4];
                vv = *(const float4*)&vbase[(size_t)kr * HD + c4];
            } else {
                kv = make_float4(0.f, 0.f, 0.f, 0.f);
                vv = kv;
            }
            *(float4*)&sK[row * AP + c4] = kv;
            *(float4*)&sV[row * AP + c4] = vv;
        }
        __syncthreads();

        float s[8][4];
        #pragma unroll
        for (int nj = 0; nj < 8; nj++)
            #pragma unroll
            for (int r = 0; r < 4; r++) s[nj][r] = 0.f;

        #pragma unroll
        for (int c = 0; c < 8; c++) {
            #pragma unroll
            for (int nj = 0; nj < 8; nj++) {
                uint32_t bf[2];
                int ka = (8 * nj + g) * AP + 8 * c + tg;
                bf[0] = __float_as_uint(sK[ka]);
                bf[1] = __float_as_uint(sK[ka + 4]);
                mma_tf32(s[nj], qf[c], bf);
            }
        }

        #pragma unroll
        for (int nj = 0; nj < 8; nj++) {
            int kc = k0 + 8 * nj + 2 * tg;
            float2 r0v = *(const float2*)&rp0[kc];
            float2 r1v = *(const float2*)&rp1[kc];
            s[nj][0] += r0v.x; s[nj][1] += r0v.y;
            s[nj][2] += r1v.x; s[nj][3] += r1v.y;
        }
        if (k0 + AK > SEQ) {
            #pragma unroll
            for (int nj = 0; nj < 8; nj++) {
                int kc = k0 + 8 * nj + 2 * tg;
                if (kc     >= SEQ) { s[nj][0] = -3.0e38f; s[nj][2] = -3.0e38f; }
                if (kc + 1 >= SEQ) { s[nj][1] = -3.0e38f; s[nj][3] = -3.0e38f; }
            }
        }

        float tm0 = -3.0e38f, tm1 = -3.0e38f;
        #pragma unroll
        for (int nj = 0; nj < 8; nj++) {
            tm0 = fmaxf(tm0, fmaxf(s[nj][0], s[nj][1]));
            tm1 = fmaxf(tm1, fmaxf(s[nj][2], s[nj][3]));
        }
        #pragma unroll
        for (int off = 1; off <= 2; off <<= 1) {
            tm0 = fmaxf(tm0, __shfl_xor_sync(0xffffffffu, tm0, off));
            tm1 = fmaxf(tm1, __shfl_xor_sync(0xffffffffu, tm1, off));
        }
        float mn0 = fmaxf(m0r, tm0);
        float mn1 = fmaxf(m1r, tm1);
        float c0 = fexp2(m0r - mn0);
        float c1 = fexp2(m1r - mn1);
        m0r = mn0; m1r = mn1;

        float rs0 = 0.f, rs1 = 0.f;
        #pragma unroll
        for (int nj = 0; nj < 8; nj++) {
            s[nj][0] = fexp2(s[nj][0] - mn0);
            s[nj][1] = fexp2(s[nj][1] - mn0);
            s[nj][2] = fexp2(s[nj][2] - mn1);
            s[nj][3] = fexp2(s[nj][3] - mn1);
            rs0 += s[nj][0] + s[nj][1];
            rs1 += s[nj][2] + s[nj][3];
        }
        #pragma unroll
        for (int off = 1; off <= 2; off <<= 1) {
            rs0 += __shfl_xor_sync(0xffffffffu, rs0, off);
            rs1 += __shfl_xor_sync(0xffffffffu, rs1, off);
        }
        l0r = l0r * c0 + rs0;
        l1r = l1r * c1 + rs1;
        #pragma unroll
        for (int nj = 0; nj < 8; nj++) {
            o[nj][0] *= c0; o[nj][1] *= c0;
            o[nj][2] *= c1; o[nj][3] *= c1;
        }

        #pragma unroll
        for (int c = 0; c < 8; c++) {
            uint32_t pa[4];
            pa[0] = cvt_tf32_u(s[c][0]);
            pa[1] = cvt_tf32_u(s[c][2]);
            pa[2] = cvt_tf32_u(s[c][1]);
            pa[3] = cvt_tf32_u(s[c][3]);
            #pragma unroll
            for (int nj = 0; nj < 8; nj++) {
                uint32_t bf[2];
                int va = (8 * c + 2 * tg) * AP + 8 * nj + g;
                bf[0] = __float_as_uint(sV[va]);
                bf[1] = __float_as_uint(sV[va + AP]);
                mma_tf32(o[nj], pa, bf);
            }
        }
    }

    // epilogue: normalize, tf32-round, write g_ao in k-PERMUTED order for the
    // proj GEMM. Local d-pair l=2tg,2tg+1 -> positions p(l)=(l&3)*2+(l>>2).
    const int p0 = ((2 * tg) & 3) * 2 + ((2 * tg) >> 2);
    const int p1 = ((2 * tg + 1) & 3) * 2 + ((2 * tg + 1) >> 2);
    float inv0 = 1.0f / l0r;
    float inv1 = 1.0f / l1r;
    if (qi0 < SEQ) {
        float* dst = &g_ao[((size_t)(b * SEQ + qi0)) * EMB + h * HD];
        #pragma unroll
        for (int nj = 0; nj < 8; nj++) {
            dst[8 * nj + p0] = cvt_tf32(o[nj][0] * inv0);
            dst[8 * nj + p1] = cvt_tf32(o[nj][1] * inv0);
        }
    }
    if (qi1 < SEQ) {
        float* dst = &g_ao[((size_t)(b * SEQ + qi1)) * EMB + h * HD];
        #pragma unroll
        for (int nj = 0; nj < 8; nj++) {
            dst[8 * nj + p0] = cvt_tf32(o[nj][2] * inv1);
            dst[8 * nj + p1] = cvt_tf32(o[nj][3] * inv1);
        }
    }
}

// ---------------------------------------------------------------------------
// Launch
// ---------------------------------------------------------------------------
extern "C" void kernel_launch(void* const* d_in, const int* in_sizes, int n_in,
                              void* d_out, int out_size)
{
    const float* x         = (const float*)d_in[0];
    const float* qkv_w     = (const float*)d_in[1];
    const float* q_bias    = (const float*)d_in[2];
    const float* v_bias    = (const float*)d_in[3];
    const float* rpb_table = (const float*)d_in[4];
    const float* proj_w    = (const float*)d_in[5];
    const float* proj_b    = (const float*)d_in[6];
    const int*   rel_idx   = (const int*)d_in[7];
    float*       out       = (float*)d_out;

    cudaFuncSetAttribute(attn_tc_kernel,
                         cudaFuncAttributeMaxDynamicSharedMemorySize,
                         ATT_SMEM_BYTES);
    cudaFuncSetAttribute(qkv_gemm_tc,
                         cudaFuncAttributeMaxDynamicSharedMemorySize,
                         GEMM_SMEM_BYTES);
    cudaFuncSetAttribute(proj_gemm_tc,
                         cudaFuncAttributeMaxDynamicSharedMemorySize,
                         GEMM_SMEM_BYTES);

    float *p_xt, *p_wt, *p_pwt;
    cudaGetSymbolAddress((void**)&p_xt,  g_xt);
    cudaGetSymbolAddress((void**)&p_wt,  g_wt);
    cudaGetSymbolAddress((void**)&p_pwt, g_pwt);

    // 0) tf32 round + k-permute of GEMM inputs
    {
        int ng = MROWS * EMB / 8;
        tf32_round_perm_kernel<<<(ng + 255) / 256, 256>>>(x, p_xt, ng);
        ng = NQKV * EMB / 8;
        tf32_round_perm_kernel<<<(ng + 255) / 256, 256>>>(qkv_w, p_wt, ng);
        ng = EMB * EMB / 8;
        tf32_round_perm_kernel<<<(ng + 255) / 256, 256>>>(proj_w, p_pwt, ng);
    }
    // 1) RPB gather (x log2e)
    {
        const int total = NH * SEQ * SEQ;
        rpb_gather_kernel<<<(total + 255) / 256, 256>>>(rpb_table, rel_idx);
    }
    // 2) QKV GEMM
    {
        dim3 grid((MROWS + 127) / 128, NQKV / 128);
        qkv_gemm_tc<<<grid, 256, GEMM_SMEM_BYTES>>>(q_bias, v_bias);
    }
    // 3) tf32 flash attention
    {
        dim3 grid((SEQ + AQ - 1) / AQ, NH, BATCH);
        attn_tc_kernel<<<grid, 256, ATT_SMEM_BYTES>>>();
    }
    // 4) projection
    {
        dim3 grid((MROWS + 127) / 128, EMB / 128);
        proj_gemm_tc<<<grid, 256, GEMM_SMEM_BYTES>>>(proj_b, out);
    }
}

// round 14
// speedup vs baseline: 1.1207x; 1.1207x over previous
#include <cuda_runtime.h>
#include <cstdint>

// Problem constants
#define BATCH 8
#define SEQ   1025
#define EMB   768
#define NH    12
#define HD    64
#define MROWS (BATCH*SEQ)      // 8200
#define NQKV  (3*EMB)          // 2304
#define RPP   1026             // RPB row pitch (even -> float2-aligned rows)
#define LOG2E 1.4426950408889634f

// ---------------------------------------------------------------------------
// Scratch (device globals; allocation-free per harness rules)
// ---------------------------------------------------------------------------
__device__ __align__(16) float g_q  [BATCH*NH*SEQ*HD];   // q pre-scaled (x log2e), tf32
__device__ __align__(16) float g_k  [BATCH*NH*SEQ*HD];   // tf32
__device__ __align__(16) float g_v  [BATCH*NH*SEQ*HD];   // tf32
__device__ __align__(16) float g_ao [MROWS*EMB];         // attn out, tf32, k-permuted
__device__ __align__(16) float g_rpb[NH*SEQ*RPP + 256];  // [H][N][RPP] x log2e
__device__ __align__(16) float g_xt [MROWS*EMB];         // X  tf32, k-permuted
__device__ __align__(16) float g_wt [NQKV*EMB];          // qkv_w tf32, k-permuted
__device__ __align__(16) float g_pwt[EMB*EMB];           // proj_w tf32, k-permuted

// ---------------------------------------------------------------------------
// helpers
// ---------------------------------------------------------------------------
__device__ __forceinline__ float cvt_tf32(float x) {
    uint32_t u;
    asm("cvt.rna.tf32.f32 %0, %1;" : "=r"(u) : "f"(x));
    return __uint_as_float(u);
}
__device__ __forceinline__ uint32_t cvt_tf32_u(float x) {
    uint32_t u;
    asm("cvt.rna.tf32.f32 %0, %1;" : "=r"(u) : "f"(x));
    return u;
}
__device__ __forceinline__ float fexp2(float x) {
    float y;
    asm("ex2.approx.f32 %0, %1;" : "=f"(y) : "f"(x));
    return y;
}

__device__ __forceinline__ void mma_tf32(float* d,
                                         const uint32_t* a,
                                         const uint32_t* b)
{
    asm volatile(
        "mma.sync.aligned.m16n8k8.row.col.f32.tf32.tf32.f32 "
        "{%0,%1,%2,%3}, {%4,%5,%6,%7}, {%8,%9}, {%0,%1,%2,%3};\n"
        : "+f"(d[0]), "+f"(d[1]), "+f"(d[2]), "+f"(d[3])
        : "r"(a[0]), "r"(a[1]), "r"(a[2]), "r"(a[3]),
          "r"(b[0]), "r"(b[1]));
}

__device__ __forceinline__ void cp_async16(void* smem_dst, const void* gptr) {
    uint32_t sa = (uint32_t)__cvta_generic_to_shared(smem_dst);
    asm volatile("cp.async.cg.shared.global [%0], [%1], 16;\n"
                 :: "r"(sa), "l"(gptr));
}
#define CP_COMMIT()  asm volatile("cp.async.commit_group;\n")
#define CP_WAIT(N)   asm volatile("cp.async.wait_group %0;\n" :: "n"(N))

// ---------------------------------------------------------------------------
// Kernel 0: tf32 round + k-group permute.
// Within each 8-float k-group, dst order = [k0,k4,k1,k5,k2,k6,k3,k7]:
// thread (g,tg)'s mma fragment pair (k=tg, k=tg+4) becomes one float2.
// ---------------------------------------------------------------------------
__global__ void tf32_round_perm_kernel(const float* __restrict__ src,
                                       float* __restrict__ dst, int ngrp)
{
    int i = blockIdx.x * blockDim.x + threadIdx.x;
    if (i >= ngrp) return;
    float4 a = *(const float4*)&src[8 * i];      // k0..k3
    float4 b = *(const float4*)&src[8 * i + 4];  // k4..k7
    float4 lo = make_float4(cvt_tf32(a.x), cvt_tf32(b.x),
                            cvt_tf32(a.y), cvt_tf32(b.y));
    float4 hi = make_float4(cvt_tf32(a.z), cvt_tf32(b.z),
                            cvt_tf32(a.w), cvt_tf32(b.w));
    *(float4*)&dst[8 * i]     = lo;
    *(float4*)&dst[8 * i + 4] = hi;
}

// ---------------------------------------------------------------------------
// Kernel 1: gather rel-pos bias -> dense [H][N][RPP], scaled by log2(e)
// ---------------------------------------------------------------------------
__global__ void rpb_gather_kernel(const float* __restrict__ table,
                                  const int* __restrict__ relidx)
{
    int t = blockIdx.x * blockDim.x + threadIdx.x;
    const int total = NH * SEQ * SEQ;
    if (t >= total) return;
    int h  = t / (SEQ * SEQ);
    int qk = t - h * (SEQ * SEQ);
    int q  = qk / SEQ;
    int k  = qk - q * SEQ;
    g_rpb[((size_t)h * SEQ + q) * RPP + k] = table[relidx[qk] * NH + h] * LOG2E;
}

// ---------------------------------------------------------------------------
// tf32 TC GEMM: 128x128 tile, BK=32, 2-stage cp.async (R12 loop structure).
// Operands pre-rounded AND k-permuted. Pitch 40 -> LDS.64 fragment loads are
// conflict-free: bank-pair = (20g + tg) mod 16 = (4g + tg), distinct within
// each 16-lane phase for both A and B patterns.
// ---------------------------------------------------------------------------
#define GP 40
#define GSTG (128 * GP)
#define GEMM_SMEM_BYTES (4 * GSTG * 4)   // 81920 B
#define KBLK (EMB / 32)                  // 24

__device__ __forceinline__ void gemm_stage_load(
    float* As, float* Bs, const float* __restrict__ Agm,
    const float* __restrict__ Bgm, int m0, int n0, int k0, int tid)
{
    #pragma unroll
    for (int r = 0; r < 4; r++) {
        int f   = tid + r * 256;
        int row = f >> 3;
        int c4  = (f & 7) << 2;
        int gr  = m0 + row; if (gr > MROWS - 1) gr = MROWS - 1;
        cp_async16(&As[row * GP + c4], &Agm[(size_t)gr * EMB + k0 + c4]);
        cp_async16(&Bs[row * GP + c4], &Bgm[(size_t)(n0 + row) * EMB + k0 + c4]);
    }
}

__device__ __forceinline__ void gemm_stage_compute(
    const float* As, const float* Bs, float acc[4][4][4],
    int wm, int wn, int g, int tg)
{
    #pragma unroll
    for (int ks = 0; ks < 4; ks++) {
        const int kb = ks * 8 + 2 * tg;
        uint32_t afr[4][4];
        #pragma unroll
        for (int mi = 0; mi < 4; mi++) {
            float2 lo = *(const float2*)&As[(wm + mi * 16 + g) * GP + kb];
            float2 hi = *(const float2*)&As[(wm + mi * 16 + g + 8) * GP + kb];
            afr[mi][0] = __float_as_uint(lo.x);  // (row g,   k=tg)
            afr[mi][1] = __float_as_uint(hi.x);  // (row g+8, k=tg)
            afr[mi][2] = __float_as_uint(lo.y);  // (row g,   k=tg+4)
            afr[mi][3] = __float_as_uint(hi.y);  // (row g+8, k=tg+4)
        }
        uint32_t bfr[4][2];
        #pragma unroll
        for (int ni = 0; ni < 4; ni++) {
            float2 bv = *(const float2*)&Bs[(wn + ni * 8 + g) * GP + kb];
            bfr[ni][0] = __float_as_uint(bv.x);
            bfr[ni][1] = __float_as_uint(bv.y);
        }
        #pragma unroll
        for (int mi = 0; mi < 4; mi++)
            #pragma unroll
            for (int ni = 0; ni < 4; ni++)
                mma_tf32(acc[mi][ni], afr[mi], bfr[ni]);
    }
}

// Kernel 2: QKV  C[M,2304] = Xt @ Wt^T (+bias/scale/scatter; q gets log2e)
__global__ __launch_bounds__(256, 2)
void qkv_gemm_tc(const float* __restrict__ q_bias,
                 const float* __restrict__ v_bias)
{
    extern __shared__ float smp[];
    const int m0  = blockIdx.x * 128;
    const int n0  = blockIdx.y * 128;
    const int tid = threadIdx.x;
    const int wid  = tid >> 5;
    const int lane = tid & 31;
    const int g  = lane >> 2;
    const int tg = lane & 3;
    const int wm = (wid >> 2) * 64;
    const int wn = (wid & 3) * 32;

    float acc[4][4][4];
    #pragma unroll
    for (int mi = 0; mi < 4; mi++)
        #pragma unroll
        for (int ni = 0; ni < 4; ni++)
            #pragma unroll
            for (int r = 0; r < 4; r++) acc[mi][ni][r] = 0.f;

    gemm_stage_load(smp, smp + GSTG, g_xt, g_wt, m0, n0, 0, tid);
    CP_COMMIT();

    for (int it = 0; it < KBLK; it++) {
        float* As = smp + (it & 1) * 2 * GSTG;
        if (it + 1 < KBLK) {
            float* An = smp + ((it + 1) & 1) * 2 * GSTG;
            gemm_stage_load(An, An + GSTG, g_xt, g_wt, m0, n0,
                            (it + 1) * 32, tid);
            CP_COMMIT();
            CP_WAIT(1);
        } else {
            CP_WAIT(0);
        }
        __syncthreads();
        gemm_stage_compute(As, As + GSTG, acc, wm, wn, g, tg);
        __syncthreads();
    }

    const float scale = 0.125f * LOG2E;
    #pragma unroll
    for (int mi = 0; mi < 4; mi++) {
        #pragma unroll
        for (int h2 = 0; h2 < 2; h2++) {
            int gr = m0 + wm + mi * 16 + g + h2 * 8;
            if (gr >= MROWS) continue;
            int b = gr / SEQ;
            int n = gr - b * SEQ;
            #pragma unroll
            for (int ni = 0; ni < 4; ni++) {
                int gc    = n0 + wn + ni * 8 + 2 * tg;
                int which = gc / EMB;
                int rem   = gc - which * EMB;
                int h     = rem >> 6;
                int d     = rem & 63;
                float v0 = acc[mi][ni][h2 * 2 + 0];
                float v1 = acc[mi][ni][h2 * 2 + 1];
                size_t off = ((size_t)(b * NH + h) * SEQ + n) * HD + d;
                if (which == 0) {
                    *(float2*)&g_q[off] =
                        make_float2(cvt_tf32((v0 + q_bias[rem]) * scale),
                                    cvt_tf32((v1 + q_bias[rem + 1]) * scale));
                } else if (which == 1) {
                    *(float2*)&g_k[off] =
                        make_float2(cvt_tf32(v0), cvt_tf32(v1));
                } else {
                    *(float2*)&g_v[off] =
                        make_float2(cvt_tf32(v0 + v_bias[rem]),
                                    cvt_tf32(v1 + v_bias[rem + 1]));
                }
            }
        }
    }
}

// Kernel 4: proj  out[M,768] = AO @ Pwt^T + bias  (AO, Pwt k-permuted)
__global__ __launch_bounds__(256, 2)
void proj_gemm_tc(const float* __restrict__ bias,
                  float* __restrict__ out)
{
    extern __shared__ float smp[];
    const int m0  = blockIdx.x * 128;
    const int n0  = blockIdx.y * 128;
    const int tid = threadIdx.x;
    const int wid  = tid >> 5;
    const int lane = tid & 31;
    const int g  = lane >> 2;
    const int tg = lane & 3;
    const int wm = (wid >> 2) * 64;
    const int wn = (wid & 3) * 32;

    float acc[4][4][4];
    #pragma unroll
    for (int mi = 0; mi < 4; mi++)
        #pragma unroll
        for (int ni = 0; ni < 4; ni++)
            #pragma unroll
            for (int r = 0; r < 4; r++) acc[mi][ni][r] = 0.f;

    gemm_stage_load(smp, smp + GSTG, g_ao, g_pwt, m0, n0, 0, tid);
    CP_COMMIT();

    for (int it = 0; it < KBLK; it++) {
        float* As = smp + (it & 1) * 2 * GSTG;
        if (it + 1 < KBLK) {
            float* An = smp + ((it + 1) & 1) * 2 * GSTG;
            gemm_stage_load(An, An + GSTG, g_ao, g_pwt, m0, n0,
                            (it + 1) * 32, tid);
            CP_COMMIT();
            CP_WAIT(1);
        } else {
            CP_WAIT(0);
        }
        __syncthreads();
        gemm_stage_compute(As, As + GSTG, acc, wm, wn, g, tg);
        __syncthreads();
    }

    #pragma unroll
    for (int mi = 0; mi < 4; mi++) {
        #pragma unroll
        for (int h2 = 0; h2 < 2; h2++) {
            int gr = m0 + wm + mi * 16 + g + h2 * 8;
            if (gr >= MROWS) continue;
            #pragma unroll
            for (int ni = 0; ni < 4; ni++) {
                int gc = n0 + wn + ni * 8 + 2 * tg;
                *(float2*)&out[(size_t)gr * EMB + gc] =
                    make_float2(acc[mi][ni][h2 * 2 + 0] + bias[gc],
                                acc[mi][ni][h2 * 2 + 1] + bias[gc + 1]);
            }
        }
    }
}

// ---------------------------------------------------------------------------
// Kernel 3: tf32 tensor-core flash attention (scores in log2 domain)
// ---------------------------------------------------------------------------
#define AQ 128
#define AK 64
#define AP 68
#define ATT_SMEM_BYTES ((AQ*AP + 2*AK*AP) * 4)   // 69632

__global__ __launch_bounds__(256, 2)
void attn_tc_kernel()
{
    extern __shared__ float sm[];
    float* sQ = sm;                 // [128][68]
    float* sK = sQ + AQ * AP;       // [64][68]
    float* sV = sK + AK * AP;       // [64][68]

    const int qt = blockIdx.x;
    const int h  = blockIdx.y;
    const int b  = blockIdx.z;
    const int q0 = qt * AQ;
    const int tid  = threadIdx.x;
    const int w    = tid >> 5;
    const int lane = tid & 31;
    const int g  = lane >> 2;
    const int tg = lane & 3;

    const size_t bh = (size_t)(b * NH + h) * SEQ * HD;
    const float* qbase = g_q + bh;
    const float* kbase = g_k + bh;
    const float* vbase = g_v + bh;

    for (int f = tid; f < AQ * 16; f += 256) {
        int row = f >> 4;
        int c4  = (f & 15) << 2;
        int qr  = q0 + row;
        float4 v4;
        if (qr < SEQ) v4 = *(const float4*)&qbase[(size_t)qr * HD + c4];
        else          v4 = make_float4(0.f, 0.f, 0.f, 0.f);
        *(float4*)&sQ[row * AP + c4] = v4;
    }
    __syncthreads();

    uint32_t qf[8][4];
    #pragma unroll
    for (int c = 0; c < 8; c++) {
        int base = (16 * w + g) * AP + 8 * c + tg;
        qf[c][0] = __float_as_uint(sQ[base]);
        qf[c][1] = __float_as_uint(sQ[base + 8 * AP]);
        qf[c][2] = __float_as_uint(sQ[base + 4]);
        qf[c][3] = __float_as_uint(sQ[base + 8 * AP + 4]);
    }

    const int qi0 = q0 + 16 * w + g;
    const int qi1 = qi0 + 8;
    const int qc0 = (qi0 < SEQ) ? qi0 : (SEQ - 1);
    const int qc1 = (qi1 < SEQ) ? qi1 : (SEQ - 1);
    const float* rp0 = g_rpb + ((size_t)h * SEQ + qc0) * RPP;
    const float* rp1 = g_rpb + ((size_t)h * SEQ + qc1) * RPP;

    float o[8][4];
    #pragma unroll
    for (int nj = 0; nj < 8; nj++)
        #pragma unroll
        for (int r = 0; r < 4; r++) o[nj][r] = 0.f;
    float m0r = -3.0e38f, m1r = -3.0e38f;
    float l0r = 0.f,      l1r = 0.f;

    for (int k0 = 0; k0 < SEQ; k0 += AK) {
        __syncthreads();
        for (int f = tid; f < AK * 16; f += 256) {
            int row = f >> 4;
            int c4  = (f & 15) << 2;
            int kr  = k0 + row;
            float4 kv, vv;
            if (kr < SEQ) {
                kv = *(const float4*)&kbase[(size_t)kr * HD + c4];
                vv = *(const float4*)&vbase[(size_t)kr * HD + c4];
            } else {
                kv = make_float4(0.f, 0.f, 0.f, 0.f);
                vv = kv;
            }
            *(float4*)&sK[row * AP + c4] = kv;
            *(float4*)&sV[row * AP + c4] = vv;
        }
        __syncthreads();

        float s[8][4];
        #pragma unroll
        for (int nj = 0; nj < 8; nj++)
            #pragma unroll
            for (int r = 0; r < 4; r++) s[nj][r] = 0.f;

        #pragma unroll
        for (int c = 0; c < 8; c++) {
            #pragma unroll
            for (int nj = 0; nj < 8; nj++) {
                uint32_t bf[2];
                int ka = (8 * nj + g) * AP + 8 * c + tg;
                bf[0] = __float_as_uint(sK[ka]);
                bf[1] = __float_as_uint(sK[ka + 4]);
                mma_tf32(s[nj], qf[c], bf);
            }
        }

        #pragma unroll
        for (int nj = 0; nj < 8; nj++) {
            int kc = k0 + 8 * nj + 2 * tg;
            float2 r0v = *(const float2*)&rp0[kc];
            float2 r1v = *(const float2*)&rp1[kc];
            s[nj][0] += r0v.x; s[nj][1] += r0v.y;
            s[nj][2] += r1v.x; s[nj][3] += r1v.y;
        }
        if (k0 + AK > SEQ) {
            #pragma unroll
            for (int nj = 0; nj < 8; nj++) {
                int kc = k0 + 8 * nj + 2 * tg;
                if (kc     >= SEQ) { s[nj][0] = -3.0e38f; s[nj][2] = -3.0e38f; }
                if (kc + 1 >= SEQ) { s[nj][1] = -3.0e38f; s[nj][3] = -3.0e38f; }
            }
        }

        float tm0 = -3.0e38f, tm1 = -3.0e38f;
        #pragma unroll
        for (int nj = 0; nj < 8; nj++) {
            tm0 = fmaxf(tm0, fmaxf(s[nj][0], s[nj][1]));
            tm1 = fmaxf(tm1, fmaxf(s[nj][2], s[nj][3]));
        }
        #pragma unroll
        for (int off = 1; off <= 2; off <<= 1) {
            tm0 = fmaxf(tm0, __shfl_xor_sync(0xffffffffu, tm0, off));
            tm1 = fmaxf(tm1, __shfl_xor_sync(0xffffffffu, tm1, off));
        }
        float mn0 = fmaxf(m0r, tm0);
        float mn1 = fmaxf(m1r, tm1);
        float c0 = fexp2(m0r - mn0);
        float c1 = fexp2(m1r - mn1);
        m0r = mn0; m1r = mn1;

        float rs0 = 0.f, rs1 = 0.f;
        #pragma unroll
        for (int nj = 0; nj < 8; nj++) {
            s[nj][0] = fexp2(s[nj][0] - mn0);
            s[nj][1] = fexp2(s[nj][1] - mn0);
            s[nj][2] = fexp2(s[nj][2] - mn1);
            s[nj][3] = fexp2(s[nj][3] - mn1);
            rs0 += s[nj][0] + s[nj][1];
            rs1 += s[nj][2] + s[nj][3];
        }
        #pragma unroll
        for (int off = 1; off <= 2; off <<= 1) {
            rs0 += __shfl_xor_sync(0xffffffffu, rs0, off);
            rs1 += __shfl_xor_sync(0xffffffffu, rs1, off);
        }
        l0r = l0r * c0 + rs0;
        l1r = l1r * c1 + rs1;
        #pragma unroll
        for (int nj = 0; nj < 8; nj++) {
            o[nj][0] *= c0; o[nj][1] *= c0;
            o[nj][2] *= c1; o[nj][3] *= c1;
        }

        #pragma unroll
        for (int c = 0; c < 8; c++) {
            uint32_t pa[4];
            pa[0] = cvt_tf32_u(s[c][0]);
            pa[1] = cvt_tf32_u(s[c][2]);
            pa[2] = cvt_tf32_u(s[c][1]);
            pa[3] = cvt_tf32_u(s[c][3]);
            #pragma unroll
            for (int nj = 0; nj < 8; nj++) {
                uint32_t bf[2];
                int va = (8 * c + 2 * tg) * AP + 8 * nj + g;
                bf[0] = __float_as_uint(sV[va]);
                bf[1] = __float_as_uint(sV[va + AP]);
                mma_tf32(o[nj], pa, bf);
            }
        }
    }

    // epilogue: normalize, tf32-round, write g_ao in k-PERMUTED order for the
    // proj GEMM. Local d-pair l=2tg,2tg+1 -> positions p(l)=(l&3)*2+(l>>2).
    const int p0 = ((2 * tg) & 3) * 2 + ((2 * tg) >> 2);
    const int p1 = ((2 * tg + 1) & 3) * 2 + ((2 * tg + 1) >> 2);
    float inv0 = 1.0f / l0r;
    float inv1 = 1.0f / l1r;
    if (qi0 < SEQ) {
        float* dst = &g_ao[((size_t)(b * SEQ + qi0)) * EMB + h * HD];
        #pragma unroll
        for (int nj = 0; nj < 8; nj++) {
            dst[8 * nj + p0] = cvt_tf32(o[nj][0] * inv0);
            dst[8 * nj + p1] = cvt_tf32(o[nj][1] * inv0);
        }
    }
    if (qi1 < SEQ) {
        float* dst = &g_ao[((size_t)(b * SEQ + qi1)) * EMB + h * HD];
        #pragma unroll
        for (int nj = 0; nj < 8; nj++) {
            dst[8 * nj + p0] = cvt_tf32(o[nj][2] * inv1);
            dst[8 * nj + p1] = cvt_tf32(o[nj][3] * inv1);
        }
    }
}

// ---------------------------------------------------------------------------
// Launch
// ---------------------------------------------------------------------------
extern "C" void kernel_launch(void* const* d_in, const int* in_sizes, int n_in,
                              void* d_out, int out_size)
{
    const float* x         = (const float*)d_in[0];
    const float* qkv_w     = (const float*)d_in[1];
    const float* q_bias    = (const float*)d_in[2];
    const float* v_bias    = (const float*)d_in[3];
    const float* rpb_table = (const float*)d_in[4];
    const float* proj_w    = (const float*)d_in[5];
    const float* proj_b    = (const float*)d_in[6];
    const int*   rel_idx   = (const int*)d_in[7];
    float*       out       = (float*)d_out;

    cudaFuncSetAttribute(attn_tc_kernel,
                         cudaFuncAttributeMaxDynamicSharedMemorySize,
                         ATT_SMEM_BYTES);
    cudaFuncSetAttribute(qkv_gemm_tc,
                         cudaFuncAttributeMaxDynamicSharedMemorySize,
                         GEMM_SMEM_BYTES);
    cudaFuncSetAttribute(proj_gemm_tc,
                         cudaFuncAttributeMaxDynamicSharedMemorySize,
                         GEMM_SMEM_BYTES);

    float *p_xt, *p_wt, *p_pwt;
    cudaGetSymbolAddress((void**)&p_xt,  g_xt);
    cudaGetSymbolAddress((void**)&p_wt,  g_wt);
    cudaGetSymbolAddress((void**)&p_pwt, g_pwt);

    // 0) tf32 round + k-permute of GEMM inputs
    {
        int ng = MROWS * EMB / 8;
        tf32_round_perm_kernel<<<(ng + 255) / 256, 256>>>(x, p_xt, ng);
        ng = NQKV * EMB / 8;
        tf32_round_perm_kernel<<<(ng + 255) / 256, 256>>>(qkv_w, p_wt, ng);
        ng = EMB * EMB / 8;
        tf32_round_perm_kernel<<<(ng + 255) / 256, 256>>>(proj_w, p_pwt, ng);
    }
    // 1) RPB gather (x log2e)
    {
        const int total = NH * SEQ * SEQ;
        rpb_gather_kernel<<<(total + 255) / 256, 256>>>(rpb_table, rel_idx);
    }
    // 2) QKV GEMM
    {
        dim3 grid((MROWS + 127) / 128, NQKV / 128);
        qkv_gemm_tc<<<grid, 256, GEMM_SMEM_BYTES>>>(q_bias, v_bias);
    }
    // 3) tf32 flash attention
    {
        dim3 grid((SEQ + AQ - 1) / AQ, NH, BATCH);
        attn_tc_kernel<<<grid, 256, ATT_SMEM_BYTES>>>();
    }
    // 4) projection
    {
        dim3 grid((MROWS + 127) / 128, EMB / 128);
        proj_gemm_tc<<<grid, 256, GEMM_SMEM_BYTES>>>(proj_b, out);
    }
}

// round 15
// speedup vs baseline: 1.1412x; 1.0183x over previous
#include <cuda_runtime.h>
#include <cstdint>

// Problem constants
#define BATCH 8
#define SEQ   1025
#define EMB   768
#define NH    12
#define HD    64
#define MROWS (BATCH*SEQ)      // 8200
#define NQKV  (3*EMB)          // 2304
#define RPP   1026             // RPB row pitch (even -> float2-aligned rows)
#define LOG2E 1.4426950408889634f

// ---------------------------------------------------------------------------
// Scratch (device globals; allocation-free per harness rules)
// ---------------------------------------------------------------------------
__device__ __align__(16) float g_q  [BATCH*NH*SEQ*HD];   // q pre-scaled (x log2e), tf32
__device__ __align__(16) float g_k  [BATCH*NH*SEQ*HD];   // tf32
__device__ __align__(16) float g_v  [BATCH*NH*SEQ*HD];   // tf32
__device__ __align__(16) float g_ao [MROWS*EMB];         // attn out, tf32, k-permuted
__device__ __align__(16) float g_rpb[NH*SEQ*RPP + 256];  // [H][N][RPP] x log2e
__device__ __align__(16) float g_xt [MROWS*EMB];         // X  tf32, k-permuted
__device__ __align__(16) float g_wt [NQKV*EMB];          // qkv_w tf32, k-permuted
__device__ __align__(16) float g_pwt[EMB*EMB];           // proj_w tf32, k-permuted

// ---------------------------------------------------------------------------
// helpers
// ---------------------------------------------------------------------------
__device__ __forceinline__ float cvt_tf32(float x) {
    uint32_t u;
    asm("cvt.rna.tf32.f32 %0, %1;" : "=r"(u) : "f"(x));
    return __uint_as_float(u);
}
__device__ __forceinline__ uint32_t cvt_tf32_u(float x) {
    uint32_t u;
    asm("cvt.rna.tf32.f32 %0, %1;" : "=r"(u) : "f"(x));
    return u;
}
__device__ __forceinline__ float fexp2(float x) {
    float y;
    asm("ex2.approx.f32 %0, %1;" : "=f"(y) : "f"(x));
    return y;
}

__device__ __forceinline__ void mma_tf32(float* d,
                                         const uint32_t* a,
                                         const uint32_t* b)
{
    asm volatile(
        "mma.sync.aligned.m16n8k8.row.col.f32.tf32.tf32.f32 "
        "{%0,%1,%2,%3}, {%4,%5,%6,%7}, {%8,%9}, {%0,%1,%2,%3};\n"
        : "+f"(d[0]), "+f"(d[1]), "+f"(d[2]), "+f"(d[3])
        : "r"(a[0]), "r"(a[1]), "r"(a[2]), "r"(a[3]),
          "r"(b[0]), "r"(b[1]));
}

__device__ __forceinline__ void cp_async16(void* smem_dst, const void* gptr) {
    uint32_t sa = (uint32_t)__cvta_generic_to_shared(smem_dst);
    asm volatile("cp.async.cg.shared.global [%0], [%1], 16;\n"
                 :: "r"(sa), "l"(gptr));
}
#define CP_COMMIT()  asm volatile("cp.async.commit_group;\n")
#define CP_WAIT0()   asm volatile("cp.async.wait_group 0;\n")

// ---------------------------------------------------------------------------
// Kernel 0: tf32 round + k-group permute.
// Within each 8-float k-group, dst order = [k0,k4,k1,k5,k2,k6,k3,k7]:
// thread (g,tg)'s mma fragment pair (k=tg, k=tg+4) becomes one float2.
// ---------------------------------------------------------------------------
__global__ void tf32_round_perm_kernel(const float* __restrict__ src,
                                       float* __restrict__ dst, int ngrp)
{
    int i = blockIdx.x * blockDim.x + threadIdx.x;
    if (i >= ngrp) return;
    float4 a = *(const float4*)&src[8 * i];      // k0..k3
    float4 b = *(const float4*)&src[8 * i + 4];  // k4..k7
    float4 lo = make_float4(cvt_tf32(a.x), cvt_tf32(b.x),
                            cvt_tf32(a.y), cvt_tf32(b.y));
    float4 hi = make_float4(cvt_tf32(a.z), cvt_tf32(b.z),
                            cvt_tf32(a.w), cvt_tf32(b.w));
    *(float4*)&dst[8 * i]     = lo;
    *(float4*)&dst[8 * i + 4] = hi;
}

// ---------------------------------------------------------------------------
// Kernel 1: RPB gather, fast form. grid=(q, h); one block fills one dense row
// g_rpb[h][q][0..1025] with coalesced float2 writes. No div/mod in threads.
// ---------------------------------------------------------------------------
__global__ void rpb_gather_fast(const float* __restrict__ table,
                                const int* __restrict__ relidx)
{
    const int q = blockIdx.x;
    const int h = blockIdx.y;
    const int* irow = relidx + q * SEQ;
    float* orow = g_rpb + ((size_t)h * SEQ + q) * RPP;
    for (int p = threadIdx.x; p < 513; p += 256) {
        int k  = 2 * p;
        int i0 = irow[k];
        int i1 = (k + 1 < SEQ) ? irow[k + 1] : i0;
        *(float2*)&orow[k] = make_float2(table[i0 * NH + h] * LOG2E,
                                         table[i1 * NH + h] * LOG2E);
    }
}

// ---------------------------------------------------------------------------
// tf32 TC GEMM: 128x128 tile, BK=32, 2-stage cp.async, SINGLE sync per iter.
// Operands pre-rounded AND k-permuted. Pitch 40 -> LDS.64 fragment loads are
// conflict-free (bank-pair = 4g + tg, distinct per 16-lane phase).
// ---------------------------------------------------------------------------
#define GP 40
#define GSTG (128 * GP)
#define GEMM_SMEM_BYTES (4 * GSTG * 4)   // 81920 B
#define KBLK (EMB / 32)                  // 24

__device__ __forceinline__ void gemm_stage_load(
    float* As, float* Bs, const float* __restrict__ Agm,
    const float* __restrict__ Bgm, int m0, int n0, int k0, int tid)
{
    #pragma unroll
    for (int r = 0; r < 4; r++) {
        int f   = tid + r * 256;
        int row = f >> 3;
        int c4  = (f & 7) << 2;
        int gr  = m0 + row; if (gr > MROWS - 1) gr = MROWS - 1;
        cp_async16(&As[row * GP + c4], &Agm[(size_t)gr * EMB + k0 + c4]);
        cp_async16(&Bs[row * GP + c4], &Bgm[(size_t)(n0 + row) * EMB + k0 + c4]);
    }
}

__device__ __forceinline__ void gemm_stage_compute(
    const float* As, const float* Bs, float acc[4][4][4],
    int wm, int wn, int g, int tg)
{
    #pragma unroll
    for (int ks = 0; ks < 4; ks++) {
        const int kb = ks * 8 + 2 * tg;
        uint32_t afr[4][4];
        #pragma unroll
        for (int mi = 0; mi < 4; mi++) {
            float2 lo = *(const float2*)&As[(wm + mi * 16 + g) * GP + kb];
            float2 hi = *(const float2*)&As[(wm + mi * 16 + g + 8) * GP + kb];
            afr[mi][0] = __float_as_uint(lo.x);
            afr[mi][1] = __float_as_uint(hi.x);
            afr[mi][2] = __float_as_uint(lo.y);
            afr[mi][3] = __float_as_uint(hi.y);
        }
        uint32_t bfr[4][2];
        #pragma unroll
        for (int ni = 0; ni < 4; ni++) {
            float2 bv = *(const float2*)&Bs[(wn + ni * 8 + g) * GP + kb];
            bfr[ni][0] = __float_as_uint(bv.x);
            bfr[ni][1] = __float_as_uint(bv.y);
        }
        #pragma unroll
        for (int mi = 0; mi < 4; mi++)
            #pragma unroll
            for (int ni = 0; ni < 4; ni++)
                mma_tf32(acc[mi][ni], afr[mi], bfr[ni]);
    }
}

// Single-barrier mainloop: wait-all -> sync -> issue next stage -> compute.
// Safe: next-stage cp.async writes the buffer computed at it-1; every thread
// passed sync(it) only after finishing compute(it-1).
#define GEMM_MAINLOOP(Agm, Bgm)                                              \
    gemm_stage_load(smp, smp + GSTG, Agm, Bgm, m0, n0, 0, tid);              \
    CP_COMMIT();                                                             \
    for (int it = 0; it < KBLK; it++) {                                      \
        float* As = smp + (it & 1) * 2 * GSTG;                               \
        CP_WAIT0();                                                          \
        __syncthreads();                                                     \
        if (it + 1 < KBLK) {                                                 \
            float* An = smp + ((it + 1) & 1) * 2 * GSTG;                     \
            gemm_stage_load(An, An + GSTG, Agm, Bgm, m0, n0,                 \
                            (it + 1) * 32, tid);                             \
            CP_COMMIT();                                                     \
        }                                                                    \
        gemm_stage_compute(As, As + GSTG, acc, wm, wn, g, tg);               \
    }

// Kernel 2: QKV  C[M,2304] = Xt @ Wt^T (+bias/scale/scatter; q gets log2e)
__global__ __launch_bounds__(256, 2)
void qkv_gemm_tc(const float* __restrict__ q_bias,
                 const float* __restrict__ v_bias)
{
    extern __shared__ float smp[];
    const int m0  = blockIdx.x * 128;
    const int n0  = blockIdx.y * 128;
    const int tid = threadIdx.x;
    const int wid  = tid >> 5;
    const int lane = tid & 31;
    const int g  = lane >> 2;
    const int tg = lane & 3;
    const int wm = (wid >> 2) * 64;
    const int wn = (wid & 3) * 32;

    float acc[4][4][4];
    #pragma unroll
    for (int mi = 0; mi < 4; mi++)
        #pragma unroll
        for (int ni = 0; ni < 4; ni++)
            #pragma unroll
            for (int r = 0; r < 4; r++) acc[mi][ni][r] = 0.f;

    GEMM_MAINLOOP(g_xt, g_wt)

    const float scale = 0.125f * LOG2E;
    #pragma unroll
    for (int mi = 0; mi < 4; mi++) {
        #pragma unroll
        for (int h2 = 0; h2 < 2; h2++) {
            int gr = m0 + wm + mi * 16 + g + h2 * 8;
            if (gr >= MROWS) continue;
            int b = gr / SEQ;
            int n = gr - b * SEQ;
            #pragma unroll
            for (int ni = 0; ni < 4; ni++) {
                int gc    = n0 + wn + ni * 8 + 2 * tg;
                int which = gc / EMB;
                int rem   = gc - which * EMB;
                int h     = rem >> 6;
                int d     = rem & 63;
                float v0 = acc[mi][ni][h2 * 2 + 0];
                float v1 = acc[mi][ni][h2 * 2 + 1];
                size_t off = ((size_t)(b * NH + h) * SEQ + n) * HD + d;
                if (which == 0) {
                    *(float2*)&g_q[off] =
                        make_float2(cvt_tf32((v0 + q_bias[rem]) * scale),
                                    cvt_tf32((v1 + q_bias[rem + 1]) * scale));
                } else if (which == 1) {
                    *(float2*)&g_k[off] =
                        make_float2(cvt_tf32(v0), cvt_tf32(v1));
                } else {
                    *(float2*)&g_v[off] =
                        make_float2(cvt_tf32(v0 + v_bias[rem]),
                                    cvt_tf32(v1 + v_bias[rem + 1]));
                }
            }
        }
    }
}

// Kernel 4: proj  out[M,768] = AO @ Pwt^T + bias  (AO, Pwt k-permuted)
__global__ __launch_bounds__(256, 2)
void proj_gemm_tc(const float* __restrict__ bias,
                  float* __restrict__ out)
{
    extern __shared__ float smp[];
    const int m0  = blockIdx.x * 128;
    const int n0  = blockIdx.y * 128;
    const int tid = threadIdx.x;
    const int wid  = tid >> 5;
    const int lane = tid & 31;
    const int g  = lane >> 2;
    const int tg = lane & 3;
    const int wm = (wid >> 2) * 64;
    const int wn = (wid & 3) * 32;

    float acc[4][4][4];
    #pragma unroll
    for (int mi = 0; mi < 4; mi++)
        #pragma unroll
        for (int ni = 0; ni < 4; ni++)
            #pragma unroll
            for (int r = 0; r < 4; r++) acc[mi][ni][r] = 0.f;

    GEMM_MAINLOOP(g_ao, g_pwt)

    #pragma unroll
    for (int mi = 0; mi < 4; mi++) {
        #pragma unroll
        for (int h2 = 0; h2 < 2; h2++) {
            int gr = m0 + wm + mi * 16 + g + h2 * 8;
            if (gr >= MROWS) continue;
            #pragma unroll
            for (int ni = 0; ni < 4; ni++) {
                int gc = n0 + wn + ni * 8 + 2 * tg;
                *(float2*)&out[(size_t)gr * EMB + gc] =
                    make_float2(acc[mi][ni][h2 * 2 + 0] + bias[gc],
                                acc[mi][ni][h2 * 2 + 1] + bias[gc + 1]);
            }
        }
    }
}

// ---------------------------------------------------------------------------
// Kernel 3: tf32 TC flash attention, 2-stage cp.async K/V pipeline.
// Rows beyond SEQ are CLAMPED (not zeroed): S columns kc>=SEQ are masked to
// -3e38 so P=0 there, and V garbage contributes x0.
// ---------------------------------------------------------------------------
#define AQ 128
#define AK 64
#define AP 68
#define KVSTG (2 * AK * AP)   // floats per K+V stage
#define ATT_SMEM_BYTES ((AQ*AP + 2*KVSTG) * 4)   // 104448

__device__ __forceinline__ void attn_kv_load(
    float* sK, float* sV, const float* __restrict__ kbase,
    const float* __restrict__ vbase, int k0, int tid)
{
    #pragma unroll
    for (int r = 0; r < 4; r++) {
        int f   = tid + r * 256;          // 0..1023
        int row = f >> 4;                 // 0..63
        int c4  = (f & 15) << 2;          // 0..60
        int kr  = k0 + row; if (kr > SEQ - 1) kr = SEQ - 1;
        cp_async16(&sK[row * AP + c4], &kbase[(size_t)kr * HD + c4]);
        cp_async16(&sV[row * AP + c4], &vbase[(size_t)kr * HD + c4]);
    }
}

__global__ __launch_bounds__(256, 2)
void attn_tc_kernel()
{
    extern __shared__ float sm[];
    float* sQ  = sm;                  // [128][68]
    float* sKV = sm + AQ * AP;        // 2 stages of (K[64][68], V[64][68])

    const int qt = blockIdx.x;
    const int h  = blockIdx.y;
    const int b  = blockIdx.z;
    const int q0 = qt * AQ;
    const int tid  = threadIdx.x;
    const int w    = tid >> 5;
    const int lane = tid & 31;
    const int g  = lane >> 2;
    const int tg = lane & 3;

    const size_t bh = (size_t)(b * NH + h) * SEQ * HD;
    const float* qbase = g_q + bh;
    const float* kbase = g_k + bh;
    const float* vbase = g_v + bh;

    // Q tile -> smem
    for (int f = tid; f < AQ * 16; f += 256) {
        int row = f >> 4;
        int c4  = (f & 15) << 2;
        int qr  = q0 + row;
        float4 v4;
        if (qr < SEQ) v4 = *(const float4*)&qbase[(size_t)qr * HD + c4];
        else          v4 = make_float4(0.f, 0.f, 0.f, 0.f);
        *(float4*)&sQ[row * AP + c4] = v4;
    }
    // prologue: stage 0 K/V
    attn_kv_load(sKV, sKV + AK * AP, kbase, vbase, 0, tid);
    CP_COMMIT();
    __syncthreads();

    uint32_t qf[8][4];
    #pragma unroll
    for (int c = 0; c < 8; c++) {
        int base = (16 * w + g) * AP + 8 * c + tg;
        qf[c][0] = __float_as_uint(sQ[base]);
        qf[c][1] = __float_as_uint(sQ[base + 8 * AP]);
        qf[c][2] = __float_as_uint(sQ[base + 4]);
        qf[c][3] = __float_as_uint(sQ[base + 8 * AP + 4]);
    }

    const int qi0 = q0 + 16 * w + g;
    const int qi1 = qi0 + 8;
    const int qc0 = (qi0 < SEQ) ? qi0 : (SEQ - 1);
    const int qc1 = (qi1 < SEQ) ? qi1 : (SEQ - 1);
    const float* rp0 = g_rpb + ((size_t)h * SEQ + qc0) * RPP;
    const float* rp1 = g_rpb + ((size_t)h * SEQ + qc1) * RPP;

    float o[8][4];
    #pragma unroll
    for (int nj = 0; nj < 8; nj++)
        #pragma unroll
        for (int r = 0; r < 4; r++) o[nj][r] = 0.f;
    float m0r = -3.0e38f, m1r = -3.0e38f;
    float l0r = 0.f,      l1r = 0.f;

    int it = 0;
    for (int k0 = 0; k0 < SEQ; k0 += AK, it++) {
        float* sK = sKV + (it & 1) * KVSTG;
        float* sV = sK + AK * AP;
        CP_WAIT0();
        __syncthreads();
        if (k0 + AK < SEQ) {
            float* nK = sKV + ((it + 1) & 1) * KVSTG;
            attn_kv_load(nK, nK + AK * AP, kbase, vbase, k0 + AK, tid);
            CP_COMMIT();
        }

        // S = Q @ K^T
        float s[8][4];
        #pragma unroll
        for (int nj = 0; nj < 8; nj++)
            #pragma unroll
            for (int r = 0; r < 4; r++) s[nj][r] = 0.f;

        #pragma unroll
        for (int c = 0; c < 8; c++) {
            #pragma unroll
            for (int nj = 0; nj < 8; nj++) {
                uint32_t bf[2];
                int ka = (8 * nj + g) * AP + 8 * c + tg;
                bf[0] = __float_as_uint(sK[ka]);
                bf[1] = __float_as_uint(sK[ka + 4]);
                mma_tf32(s[nj], qf[c], bf);
            }
        }

        // + relative position bias
        #pragma unroll
        for (int nj = 0; nj < 8; nj++) {
            int kc = k0 + 8 * nj + 2 * tg;
            float2 r0v = *(const float2*)&rp0[kc];
            float2 r1v = *(const float2*)&rp1[kc];
            s[nj][0] += r0v.x; s[nj][1] += r0v.y;
            s[nj][2] += r1v.x; s[nj][3] += r1v.y;
        }
        // mask invalid keys (tail tile only)
        if (k0 + AK > SEQ) {
            #pragma unroll
            for (int nj = 0; nj < 8; nj++) {
                int kc = k0 + 8 * nj + 2 * tg;
                if (kc     >= SEQ) { s[nj][0] = -3.0e38f; s[nj][2] = -3.0e38f; }
                if (kc + 1 >= SEQ) { s[nj][1] = -3.0e38f; s[nj][3] = -3.0e38f; }
            }
        }

        // online softmax (log2 domain; quad reductions)
        float tm0 = -3.0e38f, tm1 = -3.0e38f;
        #pragma unroll
        for (int nj = 0; nj < 8; nj++) {
            tm0 = fmaxf(tm0, fmaxf(s[nj][0], s[nj][1]));
            tm1 = fmaxf(tm1, fmaxf(s[nj][2], s[nj][3]));
        }
        #pragma unroll
        for (int off = 1; off <= 2; off <<= 1) {
            tm0 = fmaxf(tm0, __shfl_xor_sync(0xffffffffu, tm0, off));
            tm1 = fmaxf(tm1, __shfl_xor_sync(0xffffffffu, tm1, off));
        }
        float mn0 = fmaxf(m0r, tm0);
        float mn1 = fmaxf(m1r, tm1);
        float c0 = fexp2(m0r - mn0);
        float c1 = fexp2(m1r - mn1);
        m0r = mn0; m1r = mn1;

        float rs0 = 0.f, rs1 = 0.f;
        #pragma unroll
        for (int nj = 0; nj < 8; nj++) {
            s[nj][0] = fexp2(s[nj][0] - mn0);
            s[nj][1] = fexp2(s[nj][1] - mn0);
            s[nj][2] = fexp2(s[nj][2] - mn1);
            s[nj][3] = fexp2(s[nj][3] - mn1);
            rs0 += s[nj][0] + s[nj][1];
            rs1 += s[nj][2] + s[nj][3];
        }
        #pragma unroll
        for (int off = 1; off <= 2; off <<= 1) {
            rs0 += __shfl_xor_sync(0xffffffffu, rs0, off);
            rs1 += __shfl_xor_sync(0xffffffffu, rs1, off);
        }
        l0r = l0r * c0 + rs0;
        l1r = l1r * c1 + rs1;
        #pragma unroll
        for (int nj = 0; nj < 8; nj++) {
            o[nj][0] *= c0; o[nj][1] *= c0;
            o[nj][2] *= c1; o[nj][3] *= c1;
        }

        // O += P @ V (S accum feeds the A operand directly)
        #pragma unroll
        for (int c = 0; c < 8; c++) {
            uint32_t pa[4];
            pa[0] = cvt_tf32_u(s[c][0]);
            pa[1] = cvt_tf32_u(s[c][2]);
            pa[2] = cvt_tf32_u(s[c][1]);
            pa[3] = cvt_tf32_u(s[c][3]);
            #pragma unroll
            for (int nj = 0; nj < 8; nj++) {
                uint32_t bf[2];
                int va = (8 * c + 2 * tg) * AP + 8 * nj + g;
                bf[0] = __float_as_uint(sV[va]);
                bf[1] = __float_as_uint(sV[va + AP]);
                mma_tf32(o[nj], pa, bf);
            }
        }
        __syncthreads();   // all reads of sK/sV done before next stage reuse
    }

    // epilogue: normalize, tf32-round, write g_ao in k-PERMUTED order.
    const int p0 = ((2 * tg) & 3) * 2 + ((2 * tg) >> 2);
    const int p1 = ((2 * tg + 1) & 3) * 2 + ((2 * tg + 1) >> 2);
    float inv0 = 1.0f / l0r;
    float inv1 = 1.0f / l1r;
    if (qi0 < SEQ) {
        float* dst = &g_ao[((size_t)(b * SEQ + qi0)) * EMB + h * HD];
        #pragma unroll
        for (int nj = 0; nj < 8; nj++) {
            dst[8 * nj + p0] = cvt_tf32(o[nj][0] * inv0);
            dst[8 * nj + p1] = cvt_tf32(o[nj][1] * inv0);
        }
    }
    if (qi1 < SEQ) {
        float* dst = &g_ao[((size_t)(b * SEQ + qi1)) * EMB + h * HD];
        #pragma unroll
        for (int nj = 0; nj < 8; nj++) {
            dst[8 * nj + p0] = cvt_tf32(o[nj][2] * inv1);
            dst[8 * nj + p1] = cvt_tf32(o[nj][3] * inv1);
        }
    }
}

// ---------------------------------------------------------------------------
// Launch
// ---------------------------------------------------------------------------
extern "C" void kernel_launch(void* const* d_in, const int* in_sizes, int n_in,
                              void* d_out, int out_size)
{
    const float* x         = (const float*)d_in[0];
    const float* qkv_w     = (const float*)d_in[1];
    const float* q_bias    = (const float*)d_in[2];
    const float* v_bias    = (const float*)d_in[3];
    const float* rpb_table = (const float*)d_in[4];
    const float* proj_w    = (const float*)d_in[5];
    const float* proj_b    = (const float*)d_in[6];
    const int*   rel_idx   = (const int*)d_in[7];
    float*       out       = (float*)d_out;

    cudaFuncSetAttribute(attn_tc_kernel,
                         cudaFuncAttributeMaxDynamicSharedMemorySize,
                         ATT_SMEM_BYTES);
    cudaFuncSetAttribute(qkv_gemm_tc,
                         cudaFuncAttributeMaxDynamicSharedMemorySize,
                         GEMM_SMEM_BYTES);
    cudaFuncSetAttribute(proj_gemm_tc,
                         cudaFuncAttributeMaxDynamicSharedMemorySize,
                         GEMM_SMEM_BYTES);

    float *p_xt, *p_wt, *p_pwt;
    cudaGetSymbolAddress((void**)&p_xt,  g_xt);
    cudaGetSymbolAddress((void**)&p_wt,  g_wt);
    cudaGetSymbolAddress((void**)&p_pwt, g_pwt);

    // 0) tf32 round + k-permute of GEMM inputs
    {
        int ng = MROWS * EMB / 8;
        tf32_round_perm_kernel<<<(ng + 255) / 256, 256>>>(x, p_xt, ng);
        ng = NQKV * EMB / 8;
        tf32_round_perm_kernel<<<(ng + 255) / 256, 256>>>(qkv_w, p_wt, ng);
        ng = EMB * EMB / 8;
        tf32_round_perm_kernel<<<(ng + 255) / 256, 256>>>(proj_w, p_pwt, ng);
    }
    // 1) RPB gather (x log2e), fast row-parallel form
    {
        dim3 grid(SEQ, NH);
        rpb_gather_fast<<<grid, 256>>>(rpb_table, rel_idx);
    }
    // 2) QKV GEMM
    {
        dim3 grid((MROWS + 127) / 128, NQKV / 128);
        qkv_gemm_tc<<<grid, 256, GEMM_SMEM_BYTES>>>(q_bias, v_bias);
    }
    // 3) tf32 flash attention (cp.async K/V pipeline)
    {
        dim3 grid((SEQ + AQ - 1) / AQ, NH, BATCH);
        attn_tc_kernel<<<grid, 256, ATT_SMEM_BYTES>>>();
    }
    // 4) projection
    {
        dim3 grid((MROWS + 127) / 128, EMB / 128);
        proj_gemm_tc<<<grid, 256, GEMM_SMEM_BYTES>>>(proj_b, out);
    }
}

// round 16
// speedup vs baseline: 1.1719x; 1.0270x over previous
#include <cuda_runtime.h>
#include <cstdint>

// Problem constants
#define BATCH 8
#define SEQ   1025
#define EMB   768
#define NH    12
#define HD    64
#define MROWS (BATCH*SEQ)      // 8200
#define NQKV  (3*EMB)          // 2304
#define NREL  3972             // (2*32-1)^2 + 3
#define RPP   1028             // RPB row pitch (mult of 4 -> float4 rows)
#define LOG2E 1.4426950408889634f

// ---------------------------------------------------------------------------
// Scratch (device globals; allocation-free per harness rules)
// ---------------------------------------------------------------------------
__device__ __align__(16) float g_q  [BATCH*NH*SEQ*HD];   // q pre-scaled (x log2e), tf32
__device__ __align__(16) float g_k  [BATCH*NH*SEQ*HD];   // tf32
__device__ __align__(16) float g_v  [BATCH*NH*SEQ*HD];   // tf32
__device__ __align__(16) float g_ao [MROWS*EMB];         // attn out, tf32, k-permuted
__device__ __align__(16) float g_rpb[NH*SEQ*RPP + 256];  // [H][N][RPP] x log2e
__device__ __align__(16) float g_xt [MROWS*EMB];         // X  tf32, k-permuted
__device__ __align__(16) float g_wt [NQKV*EMB];          // qkv_w tf32, k-permuted
__device__ __align__(16) float g_pwt[EMB*EMB];           // proj_w tf32, k-permuted
__device__ __align__(16) float g_tbl[NH*NREL];           // table^T x log2e

// ---------------------------------------------------------------------------
// helpers
// ---------------------------------------------------------------------------
__device__ __forceinline__ float cvt_tf32(float x) {
    uint32_t u;
    asm("cvt.rna.tf32.f32 %0, %1;" : "=r"(u) : "f"(x));
    return __uint_as_float(u);
}
__device__ __forceinline__ uint32_t cvt_tf32_u(float x) {
    uint32_t u;
    asm("cvt.rna.tf32.f32 %0, %1;" : "=r"(u) : "f"(x));
    return u;
}
__device__ __forceinline__ float fexp2(float x) {
    float y;
    asm("ex2.approx.f32 %0, %1;" : "=f"(y) : "f"(x));
    return y;
}

__device__ __forceinline__ void mma_tf32(float* d,
                                         const uint32_t* a,
                                         const uint32_t* b)
{
    asm volatile(
        "mma.sync.aligned.m16n8k8.row.col.f32.tf32.tf32.f32 "
        "{%0,%1,%2,%3}, {%4,%5,%6,%7}, {%8,%9}, {%0,%1,%2,%3};\n"
        : "+f"(d[0]), "+f"(d[1]), "+f"(d[2]), "+f"(d[3])
        : "r"(a[0]), "r"(a[1]), "r"(a[2]), "r"(a[3]),
          "r"(b[0]), "r"(b[1]));
}

__device__ __forceinline__ void cp_async16(void* smem_dst, const void* gptr) {
    uint32_t sa = (uint32_t)__cvta_generic_to_shared(smem_dst);
    asm volatile("cp.async.cg.shared.global [%0], [%1], 16;\n"
                 :: "r"(sa), "l"(gptr));
}
#define CP_COMMIT()  asm volatile("cp.async.commit_group;\n")
#define CP_WAIT0()   asm volatile("cp.async.wait_group 0;\n")

// ---------------------------------------------------------------------------
// Kernel 0 (fused prep): tf32 round + k-permute of X / qkv_w / proj_w, AND
// transposed+scaled bias table. One launch, partitioned by global thread id.
// Permute within each 8-float k-group: [k0,k4,k1,k5,k2,k6,k3,k7] so thread
// (g,tg)'s mma fragment pair (k=tg, k=tg+4) is one float2.
// ---------------------------------------------------------------------------
#define NGX (MROWS*EMB/8)
#define NGW (NQKV*EMB/8)
#define NGP (EMB*EMB/8)
#define NGALL (NGX + NGW + NGP)

__global__ void prep_kernel(const float* __restrict__ x,
                            const float* __restrict__ qkv_w,
                            const float* __restrict__ proj_w,
                            const float* __restrict__ table)
{
    int t = blockIdx.x * blockDim.x + threadIdx.x;
    if (t < NGALL) {
        const float* src; float* dst; int i;
        if (t < NGX)              { src = x;      dst = g_xt;  i = t; }
        else if (t < NGX + NGW)   { src = qkv_w;  dst = g_wt;  i = t - NGX; }
        else                      { src = proj_w; dst = g_pwt; i = t - NGX - NGW; }
        float4 a = *(const float4*)&src[8 * i];      // k0..k3
        float4 b = *(const float4*)&src[8 * i + 4];  // k4..k7
        float4 lo = make_float4(cvt_tf32(a.x), cvt_tf32(b.x),
                                cvt_tf32(a.y), cvt_tf32(b.y));
        float4 hi = make_float4(cvt_tf32(a.z), cvt_tf32(b.z),
                                cvt_tf32(a.w), cvt_tf32(b.w));
        *(float4*)&dst[8 * i]     = lo;
        *(float4*)&dst[8 * i + 4] = hi;
    } else {
        int tt = t - NGALL;
        if (tt < NH * NREL) {
            int h   = tt / NREL;
            int idx = tt - h * NREL;
            g_tbl[h * NREL + idx] = table[idx * NH + h] * LOG2E;
        }
    }
}

// ---------------------------------------------------------------------------
// Kernel 1: RPB gather v2. grid=(q, h); reads the h-row of the transposed
// scaled table (16 KB, L1-resident) and writes float4 dense rows.
// ---------------------------------------------------------------------------
__global__ void rpb_gather_fast(const int* __restrict__ relidx)
{
    const int q = blockIdx.x;
    const int h = blockIdx.y;
    const int* irow = relidx + q * SEQ;
    const float* th = g_tbl + h * NREL;
    float* orow = g_rpb + ((size_t)h * SEQ + q) * RPP;
    for (int p = threadIdx.x; p < 257; p += 256) {
        int k  = 4 * p;
        int i0 = irow[k];
        int i1 = (k + 1 < SEQ) ? irow[k + 1] : i0;
        int i2 = (k + 2 < SEQ) ? irow[k + 2] : i0;
        int i3 = (k + 3 < SEQ) ? irow[k + 3] : i0;
        *(float4*)&orow[k] = make_float4(th[i0], th[i1], th[i2], th[i3]);
    }
}

// ---------------------------------------------------------------------------
// tf32 TC GEMM: 128x128 tile, BK=32, 2-stage cp.async, SINGLE sync per iter.
// Operands pre-rounded AND k-permuted. Pitch 40 -> LDS.64 fragment loads are
// conflict-free (bank-pair = 4g + tg, distinct per 16-lane phase).
// ---------------------------------------------------------------------------
#define GP 40
#define GSTG (128 * GP)
#define GEMM_SMEM_BYTES (4 * GSTG * 4)   // 81920 B
#define KBLK (EMB / 32)                  // 24

__device__ __forceinline__ void gemm_stage_load(
    float* As, float* Bs, const float* __restrict__ Agm,
    const float* __restrict__ Bgm, int m0, int n0, int k0, int tid)
{
    #pragma unroll
    for (int r = 0; r < 4; r++) {
        int f   = tid + r * 256;
        int row = f >> 3;
        int c4  = (f & 7) << 2;
        int gr  = m0 + row; if (gr > MROWS - 1) gr = MROWS - 1;
        cp_async16(&As[row * GP + c4], &Agm[(size_t)gr * EMB + k0 + c4]);
        cp_async16(&Bs[row * GP + c4], &Bgm[(size_t)(n0 + row) * EMB + k0 + c4]);
    }
}

__device__ __forceinline__ void gemm_stage_compute(
    const float* As, const float* Bs, float acc[4][4][4],
    int wm, int wn, int g, int tg)
{
    #pragma unroll
    for (int ks = 0; ks < 4; ks++) {
        const int kb = ks * 8 + 2 * tg;
        uint32_t afr[4][4];
        #pragma unroll
        for (int mi = 0; mi < 4; mi++) {
            float2 lo = *(const float2*)&As[(wm + mi * 16 + g) * GP + kb];
            float2 hi = *(const float2*)&As[(wm + mi * 16 + g + 8) * GP + kb];
            afr[mi][0] = __float_as_uint(lo.x);
            afr[mi][1] = __float_as_uint(hi.x);
            afr[mi][2] = __float_as_uint(lo.y);
            afr[mi][3] = __float_as_uint(hi.y);
        }
        uint32_t bfr[4][2];
        #pragma unroll
        for (int ni = 0; ni < 4; ni++) {
            float2 bv = *(const float2*)&Bs[(wn + ni * 8 + g) * GP + kb];
            bfr[ni][0] = __float_as_uint(bv.x);
            bfr[ni][1] = __float_as_uint(bv.y);
        }
        #pragma unroll
        for (int mi = 0; mi < 4; mi++)
            #pragma unroll
            for (int ni = 0; ni < 4; ni++)
                mma_tf32(acc[mi][ni], afr[mi], bfr[ni]);
    }
}

#define GEMM_MAINLOOP(Agm, Bgm)                                              \
    gemm_stage_load(smp, smp + GSTG, Agm, Bgm, m0, n0, 0, tid);              \
    CP_COMMIT();                                                             \
    for (int it = 0; it < KBLK; it++) {                                      \
        float* As = smp + (it & 1) * 2 * GSTG;                               \
        CP_WAIT0();                                                          \
        __syncthreads();                                                     \
        if (it + 1 < KBLK) {                                                 \
            float* An = smp + ((it + 1) & 1) * 2 * GSTG;                     \
            gemm_stage_load(An, An + GSTG, Agm, Bgm, m0, n0,                 \
                            (it + 1) * 32, tid);                             \
            CP_COMMIT();                                                     \
        }                                                                    \
        gemm_stage_compute(As, As + GSTG, acc, wm, wn, g, tg);               \
    }

// Kernel 2: QKV  C[M,2304] = Xt @ Wt^T (+bias/scale/scatter; q gets log2e)
__global__ __launch_bounds__(256, 2)
void qkv_gemm_tc(const float* __restrict__ q_bias,
                 const float* __restrict__ v_bias)
{
    extern __shared__ float smp[];
    const int m0  = blockIdx.x * 128;
    const int n0  = blockIdx.y * 128;
    const int tid = threadIdx.x;
    const int wid  = tid >> 5;
    const int lane = tid & 31;
    const int g  = lane >> 2;
    const int tg = lane & 3;
    const int wm = (wid >> 2) * 64;
    const int wn = (wid & 3) * 32;

    float acc[4][4][4];
    #pragma unroll
    for (int mi = 0; mi < 4; mi++)
        #pragma unroll
        for (int ni = 0; ni < 4; ni++)
            #pragma unroll
            for (int r = 0; r < 4; r++) acc[mi][ni][r] = 0.f;

    GEMM_MAINLOOP(g_xt, g_wt)

    const float scale = 0.125f * LOG2E;
    #pragma unroll
    for (int mi = 0; mi < 4; mi++) {
        #pragma unroll
        for (int h2 = 0; h2 < 2; h2++) {
            int gr = m0 + wm + mi * 16 + g + h2 * 8;
            if (gr >= MROWS) continue;
            int b = gr / SEQ;
            int n = gr - b * SEQ;
            #pragma unroll
            for (int ni = 0; ni < 4; ni++) {
                int gc    = n0 + wn + ni * 8 + 2 * tg;
                int which = gc / EMB;
                int rem   = gc - which * EMB;
                int h     = rem >> 6;
                int d     = rem & 63;
                float v0 = acc[mi][ni][h2 * 2 + 0];
                float v1 = acc[mi][ni][h2 * 2 + 1];
                size_t off = ((size_t)(b * NH + h) * SEQ + n) * HD + d;
                if (which == 0) {
                    *(float2*)&g_q[off] =
                        make_float2(cvt_tf32((v0 + q_bias[rem]) * scale),
                                    cvt_tf32((v1 + q_bias[rem + 1]) * scale));
                } else if (which == 1) {
                    *(float2*)&g_k[off] =
                        make_float2(cvt_tf32(v0), cvt_tf32(v1));
                } else {
                    *(float2*)&g_v[off] =
                        make_float2(cvt_tf32(v0 + v_bias[rem]),
                                    cvt_tf32(v1 + v_bias[rem + 1]));
                }
            }
        }
    }
}

// Kernel 4: proj  out[M,768] = AO @ Pwt^T + bias  (AO, Pwt k-permuted)
__global__ __launch_bounds__(256, 2)
void proj_gemm_tc(const float* __restrict__ bias,
                  float* __restrict__ out)
{
    extern __shared__ float smp[];
    const int m0  = blockIdx.x * 128;
    const int n0  = blockIdx.y * 128;
    const int tid = threadIdx.x;
    const int wid  = tid >> 5;
    const int lane = tid & 31;
    const int g  = lane >> 2;
    const int tg = lane & 3;
    const int wm = (wid >> 2) * 64;
    const int wn = (wid & 3) * 32;

    float acc[4][4][4];
    #pragma unroll
    for (int mi = 0; mi < 4; mi++)
        #pragma unroll
        for (int ni = 0; ni < 4; ni++)
            #pragma unroll
            for (int r = 0; r < 4; r++) acc[mi][ni][r] = 0.f;

    GEMM_MAINLOOP(g_ao, g_pwt)

    #pragma unroll
    for (int mi = 0; mi < 4; mi++) {
        #pragma unroll
        for (int h2 = 0; h2 < 2; h2++) {
            int gr = m0 + wm + mi * 16 + g + h2 * 8;
            if (gr >= MROWS) continue;
            #pragma unroll
            for (int ni = 0; ni < 4; ni++) {
                int gc = n0 + wn + ni * 8 + 2 * tg;
                *(float2*)&out[(size_t)gr * EMB + gc] =
                    make_float2(acc[mi][ni][h2 * 2 + 0] + bias[gc],
                                acc[mi][ni][h2 * 2 + 1] + bias[gc + 1]);
            }
        }
    }
}

// ---------------------------------------------------------------------------
// Kernel 3: tf32 TC flash attention, 2-stage cp.async K/V pipeline.
// ---------------------------------------------------------------------------
#define AQ 128
#define AK 64
#define AP 68
#define KVSTG (2 * AK * AP)
#define ATT_SMEM_BYTES ((AQ*AP + 2*KVSTG) * 4)   // 104448

__device__ __forceinline__ void attn_kv_load(
    float* sK, float* sV, const float* __restrict__ kbase,
    const float* __restrict__ vbase, int k0, int tid)
{
    #pragma unroll
    for (int r = 0; r < 4; r++) {
        int f   = tid + r * 256;
        int row = f >> 4;
        int c4  = (f & 15) << 2;
        int kr  = k0 + row; if (kr > SEQ - 1) kr = SEQ - 1;
        cp_async16(&sK[row * AP + c4], &kbase[(size_t)kr * HD + c4]);
        cp_async16(&sV[row * AP + c4], &vbase[(size_t)kr * HD + c4]);
    }
}

__global__ __launch_bounds__(256, 2)
void attn_tc_kernel()
{
    extern __shared__ float sm[];
    float* sQ  = sm;                  // [128][68]
    float* sKV = sm + AQ * AP;        // 2 stages of (K[64][68], V[64][68])

    const int qt = blockIdx.x;
    const int h  = blockIdx.y;
    const int b  = blockIdx.z;
    const int q0 = qt * AQ;
    const int tid  = threadIdx.x;
    const int w    = tid >> 5;
    const int lane = tid & 31;
    const int g  = lane >> 2;
    const int tg = lane & 3;

    const size_t bh = (size_t)(b * NH + h) * SEQ * HD;
    const float* qbase = g_q + bh;
    const float* kbase = g_k + bh;
    const float* vbase = g_v + bh;

    for (int f = tid; f < AQ * 16; f += 256) {
        int row = f >> 4;
        int c4  = (f & 15) << 2;
        int qr  = q0 + row;
        float4 v4;
        if (qr < SEQ) v4 = *(const float4*)&qbase[(size_t)qr * HD + c4];
        else          v4 = make_float4(0.f, 0.f, 0.f, 0.f);
        *(float4*)&sQ[row * AP + c4] = v4;
    }
    attn_kv_load(sKV, sKV + AK * AP, kbase, vbase, 0, tid);
    CP_COMMIT();
    __syncthreads();

    uint32_t qf[8][4];
    #pragma unroll
    for (int c = 0; c < 8; c++) {
        int base = (16 * w + g) * AP + 8 * c + tg;
        qf[c][0] = __float_as_uint(sQ[base]);
        qf[c][1] = __float_as_uint(sQ[base + 8 * AP]);
        qf[c][2] = __float_as_uint(sQ[base + 4]);
        qf[c][3] = __float_as_uint(sQ[base + 8 * AP + 4]);
    }

    const int qi0 = q0 + 16 * w + g;
    const int qi1 = qi0 + 8;
    const int qc0 = (qi0 < SEQ) ? qi0 : (SEQ - 1);
    const int qc1 = (qi1 < SEQ) ? qi1 : (SEQ - 1);
    const float* rp0 = g_rpb + ((size_t)h * SEQ + qc0) * RPP;
    const float* rp1 = g_rpb + ((size_t)h * SEQ + qc1) * RPP;

    float o[8][4];
    #pragma unroll
    for (int nj = 0; nj < 8; nj++)
        #pragma unroll
        for (int r = 0; r < 4; r++) o[nj][r] = 0.f;
    float m0r = -3.0e38f, m1r = -3.0e38f;
    float l0r = 0.f,      l1r = 0.f;

    int it = 0;
    for (int k0 = 0; k0 < SEQ; k0 += AK, it++) {
        float* sK = sKV + (it & 1) * KVSTG;
        float* sV = sK + AK * AP;
        CP_WAIT0();
        __syncthreads();
        if (k0 + AK < SEQ) {
            float* nK = sKV + ((it + 1) & 1) * KVSTG;
            attn_kv_load(nK, nK + AK * AP, kbase, vbase, k0 + AK, tid);
            CP_COMMIT();
        }

        float s[8][4];
        #pragma unroll
        for (int nj = 0; nj < 8; nj++)
            #pragma unroll
            for (int r = 0; r < 4; r++) s[nj][r] = 0.f;

        #pragma unroll
        for (int c = 0; c < 8; c++) {
            #pragma unroll
            for (int nj = 0; nj < 8; nj++) {
                uint32_t bf[2];
                int ka = (8 * nj + g) * AP + 8 * c + tg;
                bf[0] = __float_as_uint(sK[ka]);
                bf[1] = __float_as_uint(sK[ka + 4]);
                mma_tf32(s[nj], qf[c], bf);
            }
        }

        #pragma unroll
        for (int nj = 0; nj < 8; nj++) {
            int kc = k0 + 8 * nj + 2 * tg;
            float2 r0v = *(const float2*)&rp0[kc];
            float2 r1v = *(const float2*)&rp1[kc];
            s[nj][0] += r0v.x; s[nj][1] += r0v.y;
            s[nj][2] += r1v.x; s[nj][3] += r1v.y;
        }
        if (k0 + AK > SEQ) {
            #pragma unroll
            for (int nj = 0; nj < 8; nj++) {
                int kc = k0 + 8 * nj + 2 * tg;
                if (kc     >= SEQ) { s[nj][0] = -3.0e38f; s[nj][2] = -3.0e38f; }
                if (kc + 1 >= SEQ) { s[nj][1] = -3.0e38f; s[nj][3] = -3.0e38f; }
            }
        }

        float tm0 = -3.0e38f, tm1 = -3.0e38f;
        #pragma unroll
        for (int nj = 0; nj < 8; nj++) {
            tm0 = fmaxf(tm0, fmaxf(s[nj][0], s[nj][1]));
            tm1 = fmaxf(tm1, fmaxf(s[nj][2], s[nj][3]));
        }
        #pragma unroll
        for (int off = 1; off <= 2; off <<= 1) {
            tm0 = fmaxf(tm0, __shfl_xor_sync(0xffffffffu, tm0, off));
            tm1 = fmaxf(tm1, __shfl_xor_sync(0xffffffffu, tm1, off));
        }
        float mn0 = fmaxf(m0r, tm0);
        float mn1 = fmaxf(m1r, tm1);
        float c0 = fexp2(m0r - mn0);
        float c1 = fexp2(m1r - mn1);
        m0r = mn0; m1r = mn1;

        float rs0 = 0.f, rs1 = 0.f;
        #pragma unroll
        for (int nj = 0; nj < 8; nj++) {
            s[nj][0] = fexp2(s[nj][0] - mn0);
            s[nj][1] = fexp2(s[nj][1] - mn0);
            s[nj][2] = fexp2(s[nj][2] - mn1);
            s[nj][3] = fexp2(s[nj][3] - mn1);
            rs0 += s[nj][0] + s[nj][1];
            rs1 += s[nj][2] + s[nj][3];
        }
        #pragma unroll
        for (int off = 1; off <= 2; off <<= 1) {
            rs0 += __shfl_xor_sync(0xffffffffu, rs0, off);
            rs1 += __shfl_xor_sync(0xffffffffu, rs1, off);
        }
        l0r = l0r * c0 + rs0;
        l1r = l1r * c1 + rs1;
        #pragma unroll
        for (int nj = 0; nj < 8; nj++) {
            o[nj][0] *= c0; o[nj][1] *= c0;
            o[nj][2] *= c1; o[nj][3] *= c1;
        }

        #pragma unroll
        for (int c = 0; c < 8; c++) {
            uint32_t pa[4];
            pa[0] = cvt_tf32_u(s[c][0]);
            pa[1] = cvt_tf32_u(s[c][2]);
            pa[2] = cvt_tf32_u(s[c][1]);
            pa[3] = cvt_tf32_u(s[c][3]);
            #pragma unroll
            for (int nj = 0; nj < 8; nj++) {
                uint32_t bf[2];
                int va = (8 * c + 2 * tg) * AP + 8 * nj + g;
                bf[0] = __float_as_uint(sV[va]);
                bf[1] = __float_as_uint(sV[va + AP]);
                mma_tf32(o[nj], pa, bf);
            }
        }
        __syncthreads();
    }

    const int p0 = ((2 * tg) & 3) * 2 + ((2 * tg) >> 2);
    const int p1 = ((2 * tg + 1) & 3) * 2 + ((2 * tg + 1) >> 2);
    float inv0 = 1.0f / l0r;
    float inv1 = 1.0f / l1r;
    if (qi0 < SEQ) {
        float* dst = &g_ao[((size_t)(b * SEQ + qi0)) * EMB + h * HD];
        #pragma unroll
        for (int nj = 0; nj < 8; nj++) {
            dst[8 * nj + p0] = cvt_tf32(o[nj][0] * inv0);
            dst[8 * nj + p1] = cvt_tf32(o[nj][1] * inv0);
        }
    }
    if (qi1 < SEQ) {
        float* dst = &g_ao[((size_t)(b * SEQ + qi1)) * EMB + h * HD];
        #pragma unroll
        for (int nj = 0; nj < 8; nj++) {
            dst[8 * nj + p0] = cvt_tf32(o[nj][2] * inv1);
            dst[8 * nj + p1] = cvt_tf32(o[nj][3] * inv1);
        }
    }
}

// ---------------------------------------------------------------------------
// Launch
// ---------------------------------------------------------------------------
extern "C" void kernel_launch(void* const* d_in, const int* in_sizes, int n_in,
                              void* d_out, int out_size)
{
    const float* x         = (const float*)d_in[0];
    const float* qkv_w     = (const float*)d_in[1];
    const float* q_bias    = (const float*)d_in[2];
    const float* v_bias    = (const float*)d_in[3];
    const float* rpb_table = (const float*)d_in[4];
    const float* proj_w    = (const float*)d_in[5];
    const float* proj_b    = (const float*)d_in[6];
    const int*   rel_idx   = (const int*)d_in[7];
    float*       out       = (float*)d_out;

    cudaFuncSetAttribute(attn_tc_kernel,
                         cudaFuncAttributeMaxDynamicSharedMemorySize,
                         ATT_SMEM_BYTES);
    cudaFuncSetAttribute(qkv_gemm_tc,
                         cudaFuncAttributeMaxDynamicSharedMemorySize,
                         GEMM_SMEM_BYTES);
    cudaFuncSetAttribute(proj_gemm_tc,
                         cudaFuncAttributeMaxDynamicSharedMemorySize,
                         GEMM_SMEM_BYTES);

    // 0) fused prep: tf32 round+permute of X/W/PW + transposed scaled table
    {
        int total = NGALL + NH * NREL;
        prep_kernel<<<(total + 255) / 256, 256>>>(x, qkv_w, proj_w, rpb_table);
    }
    // 1) RPB gather from transposed table (L1-resident rows)
    {
        dim3 grid(SEQ, NH);
        rpb_gather_fast<<<grid, 256>>>(rel_idx);
    }
    // 2) QKV GEMM
    {
        dim3 grid((MROWS + 127) / 128, NQKV / 128);
        qkv_gemm_tc<<<grid, 256, GEMM_SMEM_BYTES>>>(q_bias, v_bias);
    }
    // 3) tf32 flash attention
    {
        dim3 grid((SEQ + AQ - 1) / AQ, NH, BATCH);
        attn_tc_kernel<<<grid, 256, ATT_SMEM_BYTES>>>();
    }
    // 4) projection
    {
        dim3 grid((MROWS + 127) / 128, EMB / 128);
        proj_gemm_tc<<<grid, 256, GEMM_SMEM_BYTES>>>(proj_b, out);
    }
}